// round 1
// baseline (speedup 1.0000x reference)
#include <cuda_runtime.h>
#include <cuda_bf16.h>
#include <math.h>
#include <float.h>

// Problem constants
#define BATCH 2
#define SEQ   2048
#define DMODEL 1024
#define NHEAD 16
#define HD    64
#define M_ROWS (BATCH*SEQ)        // 4096
#define QKV_N  (3*DMODEL)         // 3072

// Scratch (device globals; allocation is forbidden)
__device__ float g_qkv[(size_t)M_ROWS * QKV_N];   // 48 MB
__device__ float g_att[(size_t)M_ROWS * DMODEL];  // 16 MB

// ---------------------------------------------------------------------------
// SGEMM with bias: C[M,N] = A[M,K] @ B[K,N] + bias[N]
// 128x128 block tile, BK=8, 256 threads, 8x8 per thread.
// Assumes M%128==0, N%128==0, K%8==0 (true for all our shapes).
// ---------------------------------------------------------------------------
__global__ __launch_bounds__(256) void sgemm_bias_kernel(
    const float* __restrict__ A, const float* __restrict__ B,
    const float* __restrict__ bias, float* __restrict__ C,
    int M, int N, int K)
{
    __shared__ float As[8][132];   // [k][m], padded
    __shared__ float Bs[8][128];   // [k][n]

    const int tid = threadIdx.x;
    const int ty = tid >> 4;       // 0..15
    const int tx = tid & 15;       // 0..15
    const int row0 = blockIdx.y * 128;
    const int col0 = blockIdx.x * 128;

    // load indexing
    const int arow = tid >> 1;            // 0..127
    const int aseg = (tid & 1) * 4;       // 0 or 4
    const int brow = tid >> 5;            // 0..7
    const int bcol = (tid & 31) * 4;      // 0..124

    const float* Ap = A + (size_t)(row0 + arow) * K + aseg;
    const float* Bp = B + (size_t)brow * N + col0 + bcol;

    float acc[8][8];
#pragma unroll
    for (int i = 0; i < 8; i++)
#pragma unroll
        for (int j = 0; j < 8; j++) acc[i][j] = 0.f;

    for (int k0 = 0; k0 < K; k0 += 8) {
        float4 av = *(const float4*)(Ap + k0);
        float4 bv = *(const float4*)(Bp + (size_t)k0 * N);
        __syncthreads();
        As[aseg + 0][arow] = av.x;
        As[aseg + 1][arow] = av.y;
        As[aseg + 2][arow] = av.z;
        As[aseg + 3][arow] = av.w;
        *(float4*)&Bs[brow][bcol] = bv;
        __syncthreads();

#pragma unroll
        for (int kk = 0; kk < 8; kk++) {
            float4 a0 = *(float4*)&As[kk][ty * 8];
            float4 a1 = *(float4*)&As[kk][ty * 8 + 4];
            float4 b0 = *(float4*)&Bs[kk][tx * 8];
            float4 b1 = *(float4*)&Bs[kk][tx * 8 + 4];
            float a[8] = {a0.x,a0.y,a0.z,a0.w,a1.x,a1.y,a1.z,a1.w};
            float b[8] = {b0.x,b0.y,b0.z,b0.w,b1.x,b1.y,b1.z,b1.w};
#pragma unroll
            for (int i = 0; i < 8; i++)
#pragma unroll
                for (int j = 0; j < 8; j++)
                    acc[i][j] = fmaf(a[i], b[j], acc[i][j]);
        }
    }

    float4 bi0 = *(const float4*)&bias[col0 + tx * 8];
    float4 bi1 = *(const float4*)&bias[col0 + tx * 8 + 4];
    float bb[8] = {bi0.x,bi0.y,bi0.z,bi0.w,bi1.x,bi1.y,bi1.z,bi1.w};

#pragma unroll
    for (int i = 0; i < 8; i++) {
        float* cp = C + (size_t)(row0 + ty * 8 + i) * N + col0 + tx * 8;
        float4 v0 = make_float4(acc[i][0]+bb[0], acc[i][1]+bb[1], acc[i][2]+bb[2], acc[i][3]+bb[3]);
        float4 v1 = make_float4(acc[i][4]+bb[4], acc[i][5]+bb[5], acc[i][6]+bb[6], acc[i][7]+bb[7]);
        *(float4*)cp = v0;
        *(float4*)(cp + 4) = v1;
    }
}

// ---------------------------------------------------------------------------
// Flash-attention style causal attention.
// Grid: (B*H, S/64). Block: 256 threads = 16x16, each thread 4x4 of a 64x64 tile.
// qkv layout: [B*S, 3072], q at +0, k at +1024, v at +2048 (per-head offset h*64).
// out layout: [B*S, 1024], head-merged (col = h*64 + d).
// Dynamic smem: Qs/Ks/Vs/Ss each 64x68 floats = 69632 bytes total.
// ---------------------------------------------------------------------------
#define AP 68   // padded row length

__global__ __launch_bounds__(256) void attn_kernel(
    const float* __restrict__ qkv, float* __restrict__ out)
{
    extern __shared__ float sm[];
    float* Qs = sm;                 // [d][r]  64x68
    float* Ks = Qs + 64 * AP;       // [d][c]  64x68
    float* Vs = Ks + 64 * AP;       // [k][c]  64x68
    float* Ss = Vs + 64 * AP;       // [r][c]  64x68

    const int bh = blockIdx.x;
    const int b  = bh >> 4;
    const int h  = bh & 15;
    const int qt = blockIdx.y;
    const int q0 = qt * 64;

    const int tid = threadIdx.x;
    const int ty = tid >> 4;
    const int tx = tid & 15;

    const float* base = qkv + (size_t)(b * SEQ) * QKV_N + h * HD;

    // Load Q (transposed: Qs[d][r])
    for (int idx = tid; idx < 64 * 64; idx += 256) {
        int r = idx >> 6, d = idx & 63;
        Qs[d * AP + r] = base[(size_t)(q0 + r) * QKV_N + d];
    }

    float o[4][4];
    float m_i[4], l_i[4];
#pragma unroll
    for (int i = 0; i < 4; i++) {
        m_i[i] = -1e30f; l_i[i] = 0.f;
#pragma unroll
        for (int j = 0; j < 4; j++) o[i][j] = 0.f;
    }

    for (int kt = 0; kt <= qt; kt++) {
        const int k0 = kt * 64;
        // Load K (transposed) and V (natural)
        for (int idx = tid; idx < 64 * 64; idx += 256) {
            int r = idx >> 6, d = idx & 63;
            size_t g = (size_t)(k0 + r) * QKV_N + d;
            Ks[d * AP + r] = base[DMODEL + g];
            Vs[r * AP + d] = base[2 * DMODEL + g];
        }
        __syncthreads();

        // S = Q K^T  (64x64x64)
        float s[4][4];
#pragma unroll
        for (int i = 0; i < 4; i++)
#pragma unroll
            for (int j = 0; j < 4; j++) s[i][j] = 0.f;

#pragma unroll 4
        for (int d = 0; d < 64; d++) {
            float4 qv = *(float4*)&Qs[d * AP + ty * 4];
            float4 kv = *(float4*)&Ks[d * AP + tx * 4];
            float qa[4] = {qv.x,qv.y,qv.z,qv.w};
            float ka[4] = {kv.x,kv.y,kv.z,kv.w};
#pragma unroll
            for (int i = 0; i < 4; i++)
#pragma unroll
                for (int j = 0; j < 4; j++)
                    s[i][j] = fmaf(qa[i], ka[j], s[i][j]);
        }

        // Causal mask (diagonal tile only: global r == q0+ty*4+i, c == k0+tx*4+j, k0==q0)
        if (kt == qt) {
#pragma unroll
            for (int i = 0; i < 4; i++)
#pragma unroll
                for (int j = 0; j < 4; j++)
                    if (tx * 4 + j > ty * 4 + i) s[i][j] = -1e30f;
        }

        // Online softmax
        float rm[4], rs[4], mn[4], sc[4];
#pragma unroll
        for (int i = 0; i < 4; i++) {
            rm[i] = fmaxf(fmaxf(s[i][0], s[i][1]), fmaxf(s[i][2], s[i][3]));
        }
#pragma unroll
        for (int off = 1; off < 16; off <<= 1) {
#pragma unroll
            for (int i = 0; i < 4; i++)
                rm[i] = fmaxf(rm[i], __shfl_xor_sync(0xffffffffu, rm[i], off));
        }
#pragma unroll
        for (int i = 0; i < 4; i++) {
            mn[i] = fmaxf(m_i[i], rm[i]);
            sc[i] = __expf(m_i[i] - mn[i]);
            rs[i] = 0.f;
#pragma unroll
            for (int j = 0; j < 4; j++) {
                s[i][j] = __expf(s[i][j] - mn[i]);
                rs[i] += s[i][j];
            }
        }
#pragma unroll
        for (int off = 1; off < 16; off <<= 1) {
#pragma unroll
            for (int i = 0; i < 4; i++)
                rs[i] += __shfl_xor_sync(0xffffffffu, rs[i], off);
        }
#pragma unroll
        for (int i = 0; i < 4; i++) {
            l_i[i] = l_i[i] * sc[i] + rs[i];
            m_i[i] = mn[i];
#pragma unroll
            for (int j = 0; j < 4; j++) o[i][j] *= sc[i];
        }

        // Store P to smem
#pragma unroll
        for (int i = 0; i < 4; i++) {
            float4 pv = make_float4(s[i][0], s[i][1], s[i][2], s[i][3]);
            *(float4*)&Ss[(ty * 4 + i) * AP + tx * 4] = pv;
        }
        __syncthreads();

        // O += P @ V
#pragma unroll 4
        for (int k = 0; k < 64; k++) {
            float4 vv = *(float4*)&Vs[k * AP + tx * 4];
            float va[4] = {vv.x,vv.y,vv.z,vv.w};
#pragma unroll
            for (int i = 0; i < 4; i++) {
                float pr = Ss[(ty * 4 + i) * AP + k];
#pragma unroll
                for (int j = 0; j < 4; j++)
                    o[i][j] = fmaf(pr, va[j], o[i][j]);
            }
        }
        __syncthreads();
    }

    // Write output: out[(b*S + q0 + r)*1024 + h*64 + c]
    float* obase = out + (size_t)(b * SEQ + q0) * DMODEL + h * HD;
#pragma unroll
    for (int i = 0; i < 4; i++) {
        float inv = 1.f / l_i[i];
        float4 v = make_float4(o[i][0]*inv, o[i][1]*inv, o[i][2]*inv, o[i][3]*inv);
        *(float4*)&obase[(size_t)(ty * 4 + i) * DMODEL + tx * 4] = v;
    }
}

// ---------------------------------------------------------------------------
extern "C" void kernel_launch(void* const* d_in, const int* in_sizes, int n_in,
                              void* d_out, int out_size)
{
    const float* hidden = (const float*)d_in[0];
    const float* w_attn = (const float*)d_in[1];
    const float* b_attn = (const float*)d_in[2];
    const float* w_proj = (const float*)d_in[3];
    const float* b_proj = (const float*)d_in[4];
    float* out = (float*)d_out;

    float* qkv = nullptr;
    float* att = nullptr;
    cudaGetSymbolAddress((void**)&qkv, g_qkv);
    cudaGetSymbolAddress((void**)&att, g_att);

    static const size_t attn_smem = 4 * 64 * AP * sizeof(float); // 69632
    cudaFuncSetAttribute(attn_kernel, cudaFuncAttributeMaxDynamicSharedMemorySize,
                         (int)attn_smem);

    // 1) QKV projection: [4096,1024] @ [1024,3072] + bias
    {
        dim3 grid(QKV_N / 128, M_ROWS / 128);
        sgemm_bias_kernel<<<grid, 256>>>(hidden, w_attn, b_attn, qkv,
                                         M_ROWS, QKV_N, DMODEL);
    }

    // 2) Causal attention
    {
        dim3 grid(BATCH * NHEAD, SEQ / 64);
        attn_kernel<<<grid, 256, attn_smem>>>(qkv, att);
    }

    // 3) Output projection: [4096,1024] @ [1024,1024] + bias
    {
        dim3 grid(DMODEL / 128, M_ROWS / 128);
        sgemm_bias_kernel<<<grid, 256>>>(att, w_proj, b_proj, out,
                                         M_ROWS, DMODEL, DMODEL);
    }
}

// round 4
// speedup vs baseline: 1.1885x; 1.1885x over previous
#include <cuda_runtime.h>
#include <cuda_bf16.h>
#include <cstdint>
#include <math.h>

// Problem constants
#define BATCH 2
#define SEQ   2048
#define DMODEL 1024
#define NHEAD 16
#define HD    64
#define M_ROWS (BATCH*SEQ)        // 4096
#define QKV_N  (3*DMODEL)         // 3072

// Scratch (device globals; allocation is forbidden)
__device__ float g_qkv[(size_t)M_ROWS * QKV_N];                        // 48 MB
__device__ float g_att[(size_t)M_ROWS * DMODEL];                       // 16 MB
__device__ float g_wT[(size_t)QKV_N * DMODEL + (size_t)DMODEL*DMODEL]; // 16 MB

// ===========================================================================
// PTX helpers
// ===========================================================================
__device__ __forceinline__ uint32_t smem_u32(const void* p) {
    uint32_t a;
    asm("{ .reg .u64 t; cvta.to.shared.u64 t, %1; cvt.u32.u64 %0, t; }"
        : "=r"(a) : "l"(p));
    return a;
}
__device__ __forceinline__ void cp_async16(uint32_t s, const void* g) {
    asm volatile("cp.async.cg.shared.global [%0], [%1], 16;" :: "r"(s), "l"(g));
}
__device__ __forceinline__ void cp_commit() {
    asm volatile("cp.async.commit_group;" ::: "memory");
}
template<int N> __device__ __forceinline__ void cp_wait() {
    asm volatile("cp.async.wait_group %0;" :: "n"(N) : "memory");
}

// tf32 mma: D[16x8] += A[16x8] * B[8x8]  (row.col)
__device__ __forceinline__ void mma_tf32(float* c, const uint32_t* a, const uint32_t* b) {
    asm volatile(
        "mma.sync.aligned.m16n8k8.row.col.f32.tf32.tf32.f32 "
        "{%0,%1,%2,%3}, {%4,%5,%6,%7}, {%8,%9}, {%0,%1,%2,%3};"
        : "+f"(c[0]), "+f"(c[1]), "+f"(c[2]), "+f"(c[3])
        : "r"(a[0]), "r"(a[1]), "r"(a[2]), "r"(a[3]), "r"(b[0]), "r"(b[1]));
}

// Split fp32 into hi (tf32-truncated) + lo (residual) for 3xTF32
__device__ __forceinline__ void tf32_split(uint32_t x, uint32_t& hi, uint32_t& lo) {
    hi = x & 0xFFFFE000u;
    lo = __float_as_uint(__uint_as_float(x) - __uint_as_float(hi));
}

// ===========================================================================
// Weight transpose: out[c][r] = in[r][c]   (in: [R][C])
// ===========================================================================
__global__ void transpose_kernel(const float* __restrict__ in, float* __restrict__ out,
                                 int R, int C) {
    __shared__ float t[32][33];
    int c0 = blockIdx.x * 32, r0 = blockIdx.y * 32;
    int tx = threadIdx.x, ty = threadIdx.y;   // 32 x 8
#pragma unroll
    for (int i = 0; i < 32; i += 8)
        t[ty + i][tx] = in[(size_t)(r0 + ty + i) * C + c0 + tx];
    __syncthreads();
#pragma unroll
    for (int i = 0; i < 32; i += 8)
        out[(size_t)(c0 + ty + i) * R + r0 + tx] = t[tx][ty + i];
}

// ===========================================================================
// 3xTF32 mma.sync GEMM: C[M,N] = A[M,K] @ BT[N,K]^T + bias[N]
// 128x128 CTA tile, 256 threads (8 warps, warp tile 64x32), BK=32,
// 3-stage cp.async pipeline. Smem rows padded to 36 floats (conflict-free).
// Each fp32 operand split hi/lo; acc += ah*bh + al*bh + ah*bl.
// ===========================================================================
#define BK 32
#define SROW 36                         // padded row stride (floats)
#define STAGE_FLOATS (2 * 128 * SROW)   // A tile + B tile
#define GSTAGES 3
#define GEMM_DYN_SMEM (GSTAGES * STAGE_FLOATS * 4)   // 110592 B

__global__ __launch_bounds__(256, 1) void gemm_tc(
    const float* __restrict__ A, const float* __restrict__ BT,
    const float* __restrict__ bias, float* __restrict__ C,
    int M, int N, int K)
{
    extern __shared__ float smem[];
    const int tid = threadIdx.x;
    const int wid = tid >> 5, lid = tid & 31;
    const int g = lid >> 2, t = lid & 3;       // group row, thread-in-group
    const int warp_m = (wid & 1) * 64;         // 2 m-warps
    const int warp_n = (wid >> 1) * 32;        // 4 n-warps
    const int row0 = blockIdx.y * 128;
    const int col0 = blockIdx.x * 128;

    const uint32_t sb = smem_u32(smem);
    const float* Abase  = A  + (size_t)row0 * K;
    const float* BTbase = BT + (size_t)col0 * K;
    const int NC = K / BK;

    auto load_chunk = [&](int c, int s) {
        const float* Ag = Abase  + c * BK;
        const float* Bg = BTbase + c * BK;
        uint32_t abase = sb + (uint32_t)(s * STAGE_FLOATS) * 4;
        uint32_t bbase = abase + 128 * SROW * 4;
#pragma unroll
        for (int i = 0; i < 4; i++) {
            int idx = i * 256 + tid;            // 0..1023
            int r = idx >> 3, q = idx & 7;      // row, 16B chunk
            uint32_t off = (uint32_t)(r * SROW + q * 4) * 4;
            cp_async16(abase + off, Ag + (size_t)r * K + q * 4);
            cp_async16(bbase + off, Bg + (size_t)r * K + q * 4);
        }
        cp_commit();
    };

#pragma unroll
    for (int c = 0; c < GSTAGES; c++) load_chunk(c, c);

    float acc[4][4][4];
#pragma unroll
    for (int mt = 0; mt < 4; mt++)
#pragma unroll
        for (int nt = 0; nt < 4; nt++)
#pragma unroll
            for (int r = 0; r < 4; r++) acc[mt][nt][r] = 0.f;

    int s = 0;
    for (int c = 0; c < NC; c++) {
        cp_wait<GSTAGES - 1>();
        __syncthreads();

        const uint32_t* As = (const uint32_t*)(smem + s * STAGE_FLOATS);
        const uint32_t* Bs = As + 128 * SROW;

#pragma unroll
        for (int kk = 0; kk < BK / 8; kk++) {
            const int kc = kk * 8;
            uint32_t ah[4][4], al[4][4];
#pragma unroll
            for (int mt = 0; mt < 4; mt++) {
                int r0 = warp_m + mt * 16 + g;
                uint32_t raw[4];
                raw[0] = As[r0 * SROW + kc + t];
                raw[1] = As[(r0 + 8) * SROW + kc + t];
                raw[2] = As[r0 * SROW + kc + t + 4];
                raw[3] = As[(r0 + 8) * SROW + kc + t + 4];
#pragma unroll
                for (int r = 0; r < 4; r++)
                    tf32_split(raw[r], ah[mt][r], al[mt][r]);
            }
#pragma unroll
            for (int nt = 0; nt < 4; nt++) {
                int n0 = warp_n + nt * 8 + g;
                uint32_t braw[2], bh[2], bl[2];
                braw[0] = Bs[n0 * SROW + kc + t];
                braw[1] = Bs[n0 * SROW + kc + t + 4];
                tf32_split(braw[0], bh[0], bl[0]);
                tf32_split(braw[1], bh[1], bl[1]);
#pragma unroll
                for (int mt = 0; mt < 4; mt++) {
                    mma_tf32(acc[mt][nt], ah[mt], bh);
                    mma_tf32(acc[mt][nt], al[mt], bh);
                    mma_tf32(acc[mt][nt], ah[mt], bl);
                }
            }
        }

        __syncthreads();
        if (c + GSTAGES < NC) load_chunk(c + GSTAGES, s);
        else { cp_commit(); }          // keep group counting aligned
        s = (s + 1 == GSTAGES) ? 0 : s + 1;
    }

    // ---- epilogue: registers -> global, + bias ----
#pragma unroll
    for (int mt = 0; mt < 4; mt++) {
        int r0 = row0 + warp_m + mt * 16 + g;
#pragma unroll
        for (int nt = 0; nt < 4; nt++) {
            int gc = col0 + warp_n + nt * 8 + 2 * t;
            float b0 = bias[gc], b1 = bias[gc + 1];
            float2 v0 = make_float2(acc[mt][nt][0] + b0, acc[mt][nt][1] + b1);
            float2 v1 = make_float2(acc[mt][nt][2] + b0, acc[mt][nt][3] + b1);
            *(float2*)&C[(size_t)r0 * N + gc] = v0;
            *(float2*)&C[(size_t)(r0 + 8) * N + gc] = v1;
        }
    }
}

// ===========================================================================
// Flash-attention style causal attention (fp32 SIMT) — unchanged (passing).
// ===========================================================================
#define AP 68

__global__ __launch_bounds__(256) void attn_kernel(
    const float* __restrict__ qkv, float* __restrict__ out)
{
    extern __shared__ float sm[];
    float* Qs = sm;
    float* Ks = Qs + 64 * AP;
    float* Vs = Ks + 64 * AP;
    float* Ss = Vs + 64 * AP;

    const int bh = blockIdx.x;
    const int b  = bh >> 4;
    const int h  = bh & 15;
    const int qt = blockIdx.y;
    const int q0 = qt * 64;

    const int tid = threadIdx.x;
    const int ty = tid >> 4;
    const int tx = tid & 15;

    const float* base = qkv + (size_t)(b * SEQ) * QKV_N + h * HD;

    for (int idx = tid; idx < 64 * 64; idx += 256) {
        int r = idx >> 6, d = idx & 63;
        Qs[d * AP + r] = base[(size_t)(q0 + r) * QKV_N + d];
    }

    float o[4][4];
    float m_i[4], l_i[4];
#pragma unroll
    for (int i = 0; i < 4; i++) {
        m_i[i] = -1e30f; l_i[i] = 0.f;
#pragma unroll
        for (int j = 0; j < 4; j++) o[i][j] = 0.f;
    }

    for (int kt = 0; kt <= qt; kt++) {
        const int k0 = kt * 64;
        for (int idx = tid; idx < 64 * 64; idx += 256) {
            int r = idx >> 6, d = idx & 63;
            size_t gidx = (size_t)(k0 + r) * QKV_N + d;
            Ks[d * AP + r] = base[DMODEL + gidx];
            Vs[r * AP + d] = base[2 * DMODEL + gidx];
        }
        __syncthreads();

        float sreg[4][4];
#pragma unroll
        for (int i = 0; i < 4; i++)
#pragma unroll
            for (int j = 0; j < 4; j++) sreg[i][j] = 0.f;

#pragma unroll 4
        for (int d = 0; d < 64; d++) {
            float4 qv = *(float4*)&Qs[d * AP + ty * 4];
            float4 kv = *(float4*)&Ks[d * AP + tx * 4];
            float qa[4] = {qv.x,qv.y,qv.z,qv.w};
            float ka[4] = {kv.x,kv.y,kv.z,kv.w};
#pragma unroll
            for (int i = 0; i < 4; i++)
#pragma unroll
                for (int j = 0; j < 4; j++)
                    sreg[i][j] = fmaf(qa[i], ka[j], sreg[i][j]);
        }

        if (kt == qt) {
#pragma unroll
            for (int i = 0; i < 4; i++)
#pragma unroll
                for (int j = 0; j < 4; j++)
                    if (tx * 4 + j > ty * 4 + i) sreg[i][j] = -1e30f;
        }

        float rm[4], rs[4], mn[4], sc[4];
#pragma unroll
        for (int i = 0; i < 4; i++)
            rm[i] = fmaxf(fmaxf(sreg[i][0], sreg[i][1]), fmaxf(sreg[i][2], sreg[i][3]));
#pragma unroll
        for (int off = 1; off < 16; off <<= 1) {
#pragma unroll
            for (int i = 0; i < 4; i++)
                rm[i] = fmaxf(rm[i], __shfl_xor_sync(0xffffffffu, rm[i], off));
        }
#pragma unroll
        for (int i = 0; i < 4; i++) {
            mn[i] = fmaxf(m_i[i], rm[i]);
            sc[i] = __expf(m_i[i] - mn[i]);
            rs[i] = 0.f;
#pragma unroll
            for (int j = 0; j < 4; j++) {
                sreg[i][j] = __expf(sreg[i][j] - mn[i]);
                rs[i] += sreg[i][j];
            }
        }
#pragma unroll
        for (int off = 1; off < 16; off <<= 1) {
#pragma unroll
            for (int i = 0; i < 4; i++)
                rs[i] += __shfl_xor_sync(0xffffffffu, rs[i], off);
        }
#pragma unroll
        for (int i = 0; i < 4; i++) {
            l_i[i] = l_i[i] * sc[i] + rs[i];
            m_i[i] = mn[i];
#pragma unroll
            for (int j = 0; j < 4; j++) o[i][j] *= sc[i];
        }

#pragma unroll
        for (int i = 0; i < 4; i++) {
            float4 pv = make_float4(sreg[i][0], sreg[i][1], sreg[i][2], sreg[i][3]);
            *(float4*)&Ss[(ty * 4 + i) * AP + tx * 4] = pv;
        }
        __syncthreads();

#pragma unroll 4
        for (int k = 0; k < 64; k++) {
            float4 vv = *(float4*)&Vs[k * AP + tx * 4];
            float va[4] = {vv.x,vv.y,vv.z,vv.w};
#pragma unroll
            for (int i = 0; i < 4; i++) {
                float pr = Ss[(ty * 4 + i) * AP + k];
#pragma unroll
                for (int j = 0; j < 4; j++)
                    o[i][j] = fmaf(pr, va[j], o[i][j]);
            }
        }
        __syncthreads();
    }

    float* obase = out + (size_t)(b * SEQ + q0) * DMODEL + h * HD;
#pragma unroll
    for (int i = 0; i < 4; i++) {
        float inv = 1.f / l_i[i];
        float4 v = make_float4(o[i][0]*inv, o[i][1]*inv, o[i][2]*inv, o[i][3]*inv);
        *(float4*)&obase[(size_t)(ty * 4 + i) * DMODEL + tx * 4] = v;
    }
}

// ===========================================================================
extern "C" void kernel_launch(void* const* d_in, const int* in_sizes, int n_in,
                              void* d_out, int out_size)
{
    const float* hidden = (const float*)d_in[0];
    const float* w_attn = (const float*)d_in[1];
    const float* b_attn = (const float*)d_in[2];
    const float* w_proj = (const float*)d_in[3];
    const float* b_proj = (const float*)d_in[4];
    float* out = (float*)d_out;

    float* qkv = nullptr;
    float* att = nullptr;
    float* wT  = nullptr;
    cudaGetSymbolAddress((void**)&qkv, g_qkv);
    cudaGetSymbolAddress((void**)&att, g_att);
    cudaGetSymbolAddress((void**)&wT,  g_wT);
    float* wTa = wT;                                   // [3072][1024]
    float* wTp = wT + (size_t)QKV_N * DMODEL;          // [1024][1024]

    static const size_t attn_smem = 4 * 64 * AP * sizeof(float);
    cudaFuncSetAttribute(attn_kernel, cudaFuncAttributeMaxDynamicSharedMemorySize,
                         (int)attn_smem);
    cudaFuncSetAttribute(gemm_tc, cudaFuncAttributeMaxDynamicSharedMemorySize,
                         GEMM_DYN_SMEM);

    // 0) Transpose weights to [N][K]
    {
        dim3 blk(32, 8);
        transpose_kernel<<<dim3(QKV_N / 32, DMODEL / 32), blk>>>(w_attn, wTa, DMODEL, QKV_N);
        transpose_kernel<<<dim3(DMODEL / 32, DMODEL / 32), blk>>>(w_proj, wTp, DMODEL, DMODEL);
    }

    // 1) QKV projection (3xtf32 mma): [4096,1024] @ [1024,3072] + bias
    {
        dim3 grid(QKV_N / 128, M_ROWS / 128);
        gemm_tc<<<grid, 256, GEMM_DYN_SMEM>>>(hidden, wTa, b_attn, qkv,
                                              M_ROWS, QKV_N, DMODEL);
    }

    // 2) Causal attention (fp32)
    {
        dim3 grid(BATCH * NHEAD, SEQ / 64);
        attn_kernel<<<grid, 256, attn_smem>>>(qkv, att);
    }

    // 3) Output projection (3xtf32 mma): [4096,1024] @ [1024,1024] + bias
    {
        dim3 grid(DMODEL / 128, M_ROWS / 128);
        gemm_tc<<<grid, 256, GEMM_DYN_SMEM>>>(att, wTp, b_proj, out,
                                              M_ROWS, DMODEL, DMODEL);
    }
}

// round 5
// speedup vs baseline: 1.6107x; 1.3552x over previous
#include <cuda_runtime.h>
#include <cuda_bf16.h>
#include <cstdint>
#include <math.h>

// Problem constants
#define BATCH 2
#define SEQ   2048
#define DMODEL 1024
#define NHEAD 16
#define HD    64
#define M_ROWS (BATCH*SEQ)        // 4096
#define QKV_N  (3*DMODEL)         // 3072

// Scratch (device globals; allocation is forbidden)
__device__ float g_qkv[(size_t)M_ROWS * QKV_N];                        // 48 MB
__device__ float g_att[(size_t)M_ROWS * DMODEL];                       // 16 MB
__device__ float g_wT[(size_t)QKV_N * DMODEL + (size_t)DMODEL*DMODEL]; // 16 MB

// ===========================================================================
// PTX helpers
// ===========================================================================
__device__ __forceinline__ uint32_t smem_u32(const void* p) {
    uint32_t a;
    asm("{ .reg .u64 t; cvta.to.shared.u64 t, %1; cvt.u32.u64 %0, t; }"
        : "=r"(a) : "l"(p));
    return a;
}
__device__ __forceinline__ void cp_async16(uint32_t s, const void* g) {
    asm volatile("cp.async.cg.shared.global [%0], [%1], 16;" :: "r"(s), "l"(g));
}
__device__ __forceinline__ void cp_commit() {
    asm volatile("cp.async.commit_group;" ::: "memory");
}
template<int N> __device__ __forceinline__ void cp_wait() {
    asm volatile("cp.async.wait_group %0;" :: "n"(N) : "memory");
}

// tf32 mma: D[16x8] += A[16x8] * B[8x8]  (row.col)
__device__ __forceinline__ void mma_tf32(float* c, const uint32_t* a, const uint32_t* b) {
    asm volatile(
        "mma.sync.aligned.m16n8k8.row.col.f32.tf32.tf32.f32 "
        "{%0,%1,%2,%3}, {%4,%5,%6,%7}, {%8,%9}, {%0,%1,%2,%3};"
        : "+f"(c[0]), "+f"(c[1]), "+f"(c[2]), "+f"(c[3])
        : "r"(a[0]), "r"(a[1]), "r"(a[2]), "r"(a[3]), "r"(b[0]), "r"(b[1]));
}

// Split fp32 into hi (tf32-truncated) + lo (residual) for 3xTF32
__device__ __forceinline__ void tf32_split(uint32_t x, uint32_t& hi, uint32_t& lo) {
    hi = x & 0xFFFFE000u;
    lo = __float_as_uint(__uint_as_float(x) - __uint_as_float(hi));
}

// ===========================================================================
// Weight transpose: out[c][r] = in[r][c]   (in: [R][C])
// ===========================================================================
__global__ void transpose_kernel(const float* __restrict__ in, float* __restrict__ out,
                                 int R, int C) {
    __shared__ float t[32][33];
    int c0 = blockIdx.x * 32, r0 = blockIdx.y * 32;
    int tx = threadIdx.x, ty = threadIdx.y;   // 32 x 8
#pragma unroll
    for (int i = 0; i < 32; i += 8)
        t[ty + i][tx] = in[(size_t)(r0 + ty + i) * C + c0 + tx];
    __syncthreads();
#pragma unroll
    for (int i = 0; i < 32; i += 8)
        out[(size_t)(c0 + ty + i) * R + r0 + tx] = t[tx][ty + i];
}

// ===========================================================================
// 3xTF32 mma.sync GEMM (unchanged, validated in R4)
// ===========================================================================
#define BK 32
#define SROW 36
#define STAGE_FLOATS (2 * 128 * SROW)
#define GSTAGES 3
#define GEMM_DYN_SMEM (GSTAGES * STAGE_FLOATS * 4)

__global__ __launch_bounds__(256, 1) void gemm_tc(
    const float* __restrict__ A, const float* __restrict__ BT,
    const float* __restrict__ bias, float* __restrict__ C,
    int M, int N, int K)
{
    extern __shared__ float smem[];
    const int tid = threadIdx.x;
    const int wid = tid >> 5, lid = tid & 31;
    const int g = lid >> 2, t = lid & 3;
    const int warp_m = (wid & 1) * 64;
    const int warp_n = (wid >> 1) * 32;
    const int row0 = blockIdx.y * 128;
    const int col0 = blockIdx.x * 128;

    const uint32_t sb = smem_u32(smem);
    const float* Abase  = A  + (size_t)row0 * K;
    const float* BTbase = BT + (size_t)col0 * K;
    const int NC = K / BK;

    auto load_chunk = [&](int c, int s) {
        const float* Ag = Abase  + c * BK;
        const float* Bg = BTbase + c * BK;
        uint32_t abase = sb + (uint32_t)(s * STAGE_FLOATS) * 4;
        uint32_t bbase = abase + 128 * SROW * 4;
#pragma unroll
        for (int i = 0; i < 4; i++) {
            int idx = i * 256 + tid;
            int r = idx >> 3, q = idx & 7;
            uint32_t off = (uint32_t)(r * SROW + q * 4) * 4;
            cp_async16(abase + off, Ag + (size_t)r * K + q * 4);
            cp_async16(bbase + off, Bg + (size_t)r * K + q * 4);
        }
        cp_commit();
    };

#pragma unroll
    for (int c = 0; c < GSTAGES; c++) load_chunk(c, c);

    float acc[4][4][4];
#pragma unroll
    for (int mt = 0; mt < 4; mt++)
#pragma unroll
        for (int nt = 0; nt < 4; nt++)
#pragma unroll
            for (int r = 0; r < 4; r++) acc[mt][nt][r] = 0.f;

    int s = 0;
    for (int c = 0; c < NC; c++) {
        cp_wait<GSTAGES - 1>();
        __syncthreads();

        const uint32_t* As = (const uint32_t*)(smem + s * STAGE_FLOATS);
        const uint32_t* Bs = As + 128 * SROW;

#pragma unroll
        for (int kk = 0; kk < BK / 8; kk++) {
            const int kc = kk * 8;
            uint32_t ah[4][4], al[4][4];
#pragma unroll
            for (int mt = 0; mt < 4; mt++) {
                int r0 = warp_m + mt * 16 + g;
                uint32_t raw[4];
                raw[0] = As[r0 * SROW + kc + t];
                raw[1] = As[(r0 + 8) * SROW + kc + t];
                raw[2] = As[r0 * SROW + kc + t + 4];
                raw[3] = As[(r0 + 8) * SROW + kc + t + 4];
#pragma unroll
                for (int r = 0; r < 4; r++)
                    tf32_split(raw[r], ah[mt][r], al[mt][r]);
            }
#pragma unroll
            for (int nt = 0; nt < 4; nt++) {
                int n0 = warp_n + nt * 8 + g;
                uint32_t braw[2], bh[2], bl[2];
                braw[0] = Bs[n0 * SROW + kc + t];
                braw[1] = Bs[n0 * SROW + kc + t + 4];
                tf32_split(braw[0], bh[0], bl[0]);
                tf32_split(braw[1], bh[1], bl[1]);
#pragma unroll
                for (int mt = 0; mt < 4; mt++) {
                    mma_tf32(acc[mt][nt], ah[mt], bh);
                    mma_tf32(acc[mt][nt], al[mt], bh);
                    mma_tf32(acc[mt][nt], ah[mt], bl);
                }
            }
        }

        __syncthreads();
        if (c + GSTAGES < NC) load_chunk(c + GSTAGES, s);
        else { cp_commit(); }
        s = (s + 1 == GSTAGES) ? 0 : s + 1;
    }

#pragma unroll
    for (int mt = 0; mt < 4; mt++) {
        int r0 = row0 + warp_m + mt * 16 + g;
#pragma unroll
        for (int nt = 0; nt < 4; nt++) {
            int gc = col0 + warp_n + nt * 8 + 2 * t;
            float b0 = bias[gc], b1 = bias[gc + 1];
            float2 v0 = make_float2(acc[mt][nt][0] + b0, acc[mt][nt][1] + b1);
            float2 v1 = make_float2(acc[mt][nt][2] + b0, acc[mt][nt][3] + b1);
            *(float2*)&C[(size_t)r0 * N + gc] = v0;
            *(float2*)&C[(size_t)(r0 + 8) * N + gc] = v1;
        }
    }
}

// ===========================================================================
// Tensor-core causal flash attention (3xTF32 mma.sync).
// Grid: (B*H, S/128). 256 threads = 8 warps, each warp owns 16 query rows.
// K-tiles of 64. K and V both used in NATIVE [s][d] layout (row.col B-frag).
// Per-array smem pads chosen for conflict-free fragment reads.
// ===========================================================================
#define TQ 128
#define TK 64
#define PADQ 68
#define PADK 68
#define PADV 72
#define PADP 68
#define ATTN_SMEM ((TQ*PADQ + TK*PADK + TK*PADV + 8*16*PADP) * 4)  // 105472 B

__global__ __launch_bounds__(256) void attn_tc(
    const float* __restrict__ qkv, float* __restrict__ out)
{
    extern __shared__ float sm[];
    float* Qs = sm;                          // [128][PADQ]  (r-major, [r][d])
    float* Ks = Qs + TQ * PADQ;              // [64][PADK]   ([s][d])
    float* Vs = Ks + TK * PADK;              // [64][PADV]   ([s][d])
    float* Ps = Vs + TK * PADV;              // per warp [16][PADP]

    const int bh = blockIdx.x;
    const int b  = bh >> 4;
    const int h  = bh & 15;
    const int qt = (gridDim.y - 1) - blockIdx.y;   // heavy tiles first
    const int q0 = qt * TQ;

    const int tid = threadIdx.x;
    const int wid = tid >> 5, lid = tid & 31;
    const int g = lid >> 2, t = lid & 3;
    const int wm = wid * 16;                 // warp's first local row
    float* Pw = Ps + wid * 16 * PADP;

    const float* base = qkv + (size_t)(b * SEQ) * QKV_N + h * HD;

    // Load Q tile [128][64]
    for (int idx = tid; idx < TQ * 16; idx += 256) {
        int r = idx >> 4, q = idx & 15;
        *(float4*)&Qs[r * PADQ + q * 4] =
            *(const float4*)&base[(size_t)(q0 + r) * QKV_N + q * 4];
    }

    float m_i[2] = {-1e30f, -1e30f};
    float l_i[2] = {0.f, 0.f};
    float oacc[8][4];
#pragma unroll
    for (int nt = 0; nt < 8; nt++)
#pragma unroll
        for (int r = 0; r < 4; r++) oacc[nt][4*0+r] = 0.f, oacc[nt][r] = 0.f;

    const int nkt = 2 * qt + 2;
    for (int kt = 0; kt < nkt; kt++) {
        const int k0 = kt * TK;
        __syncthreads();                       // protect prev-iter K/V reads
        for (int idx = tid; idx < TK * 16; idx += 256) {
            int r = idx >> 4, q = idx & 15;
            size_t gofs = (size_t)(k0 + r) * QKV_N + q * 4;
            *(float4*)&Ks[r * PADK + q * 4] = *(const float4*)&base[DMODEL + gofs];
            *(float4*)&Vs[r * PADV + q * 4] = *(const float4*)&base[2 * DMODEL + gofs];
        }
        __syncthreads();

        // Warp-level full skip: all rows of this warp < all cols of this tile
        if (k0 > q0 + wm + 15) continue;

        // ---- S = Q K^T : sacc[8 n-tiles][4] ----
        float sacc[8][4];
#pragma unroll
        for (int nt = 0; nt < 8; nt++)
#pragma unroll
            for (int r = 0; r < 4; r++) sacc[nt][r] = 0.f;

#pragma unroll
        for (int kc8 = 0; kc8 < 8; kc8++) {
            const int kc = kc8 * 8;
            uint32_t araw[4], ah[4], al[4];
            araw[0] = __float_as_uint(Qs[(wm + g)     * PADQ + kc + t]);
            araw[1] = __float_as_uint(Qs[(wm + g + 8) * PADQ + kc + t]);
            araw[2] = __float_as_uint(Qs[(wm + g)     * PADQ + kc + t + 4]);
            araw[3] = __float_as_uint(Qs[(wm + g + 8) * PADQ + kc + t + 4]);
#pragma unroll
            for (int r = 0; r < 4; r++) tf32_split(araw[r], ah[r], al[r]);
#pragma unroll
            for (int nt = 0; nt < 8; nt++) {
                uint32_t braw[2], bh[2], bl[2];
                braw[0] = __float_as_uint(Ks[(nt * 8 + g) * PADK + kc + t]);
                braw[1] = __float_as_uint(Ks[(nt * 8 + g) * PADK + kc + t + 4]);
                tf32_split(braw[0], bh[0], bl[0]);
                tf32_split(braw[1], bh[1], bl[1]);
                mma_tf32(sacc[nt], ah, bh);
                mma_tf32(sacc[nt], al, bh);
                mma_tf32(sacc[nt], ah, bl);
            }
        }

        // ---- causal mask (diagonal region only) ----
        if (k0 + TK - 1 > q0 + wm) {
            const int r0g = q0 + wm + g;
#pragma unroll
            for (int nt = 0; nt < 8; nt++) {
                int c0 = k0 + nt * 8 + 2 * t;
                if (c0     > r0g)     sacc[nt][0] = -1e30f;
                if (c0 + 1 > r0g)     sacc[nt][1] = -1e30f;
                if (c0     > r0g + 8) sacc[nt][2] = -1e30f;
                if (c0 + 1 > r0g + 8) sacc[nt][3] = -1e30f;
            }
        }

        // ---- online softmax ----
        float rm[2];
        rm[0] = fmaxf(sacc[0][0], sacc[0][1]);
        rm[1] = fmaxf(sacc[0][2], sacc[0][3]);
#pragma unroll
        for (int nt = 1; nt < 8; nt++) {
            rm[0] = fmaxf(rm[0], fmaxf(sacc[nt][0], sacc[nt][1]));
            rm[1] = fmaxf(rm[1], fmaxf(sacc[nt][2], sacc[nt][3]));
        }
#pragma unroll
        for (int off = 1; off < 4; off <<= 1) {
            rm[0] = fmaxf(rm[0], __shfl_xor_sync(0xffffffffu, rm[0], off));
            rm[1] = fmaxf(rm[1], __shfl_xor_sync(0xffffffffu, rm[1], off));
        }
        float mn0 = fmaxf(m_i[0], rm[0]), mn1 = fmaxf(m_i[1], rm[1]);
        float sc0 = __expf(m_i[0] - mn0), sc1 = __expf(m_i[1] - mn1);
        float rs0 = 0.f, rs1 = 0.f;
#pragma unroll
        for (int nt = 0; nt < 8; nt++) {
            sacc[nt][0] = __expf(sacc[nt][0] - mn0); rs0 += sacc[nt][0];
            sacc[nt][1] = __expf(sacc[nt][1] - mn0); rs0 += sacc[nt][1];
            sacc[nt][2] = __expf(sacc[nt][2] - mn1); rs1 += sacc[nt][2];
            sacc[nt][3] = __expf(sacc[nt][3] - mn1); rs1 += sacc[nt][3];
        }
#pragma unroll
        for (int off = 1; off < 4; off <<= 1) {
            rs0 += __shfl_xor_sync(0xffffffffu, rs0, off);
            rs1 += __shfl_xor_sync(0xffffffffu, rs1, off);
        }
        l_i[0] = l_i[0] * sc0 + rs0;  m_i[0] = mn0;
        l_i[1] = l_i[1] * sc1 + rs1;  m_i[1] = mn1;
#pragma unroll
        for (int nt = 0; nt < 8; nt++) {
            oacc[nt][0] *= sc0; oacc[nt][1] *= sc0;
            oacc[nt][2] *= sc1; oacc[nt][3] *= sc1;
        }

        // ---- store P (per-warp region) ----
#pragma unroll
        for (int nt = 0; nt < 8; nt++) {
            *(float2*)&Pw[g       * PADP + nt * 8 + 2 * t] = make_float2(sacc[nt][0], sacc[nt][1]);
            *(float2*)&Pw[(g + 8) * PADP + nt * 8 + 2 * t] = make_float2(sacc[nt][2], sacc[nt][3]);
        }
        __syncwarp();

        // ---- O += P @ V  (B = V native [s][d]) ----
#pragma unroll
        for (int kc8 = 0; kc8 < 8; kc8++) {
            const int kc = kc8 * 8;
            uint32_t araw[4], ah[4], al[4];
            araw[0] = __float_as_uint(Pw[g       * PADP + kc + t]);
            araw[1] = __float_as_uint(Pw[(g + 8) * PADP + kc + t]);
            araw[2] = __float_as_uint(Pw[g       * PADP + kc + t + 4]);
            araw[3] = __float_as_uint(Pw[(g + 8) * PADP + kc + t + 4]);
#pragma unroll
            for (int r = 0; r < 4; r++) tf32_split(araw[r], ah[r], al[r]);
#pragma unroll
            for (int nt = 0; nt < 8; nt++) {
                uint32_t braw[2], bh[2], bl[2];
                braw[0] = __float_as_uint(Vs[(kc + t)     * PADV + nt * 8 + g]);
                braw[1] = __float_as_uint(Vs[(kc + t + 4) * PADV + nt * 8 + g]);
                tf32_split(braw[0], bh[0], bl[0]);
                tf32_split(braw[1], bh[1], bl[1]);
                mma_tf32(oacc[nt], ah, bh);
                mma_tf32(oacc[nt], al, bh);
                mma_tf32(oacc[nt], ah, bl);
            }
        }
        __syncwarp();
    }

    // ---- write output ----
    const float inv0 = 1.f / l_i[0], inv1 = 1.f / l_i[1];
    const size_t gr0 = (size_t)(b * SEQ + q0 + wm + g);
    float* ob = out + h * HD;
#pragma unroll
    for (int nt = 0; nt < 8; nt++) {
        int gc = nt * 8 + 2 * t;
        *(float2*)&ob[gr0 * DMODEL + gc] =
            make_float2(oacc[nt][0] * inv0, oacc[nt][1] * inv0);
        *(float2*)&ob[(gr0 + 8) * DMODEL + gc] =
            make_float2(oacc[nt][2] * inv1, oacc[nt][3] * inv1);
    }
}

// ===========================================================================
extern "C" void kernel_launch(void* const* d_in, const int* in_sizes, int n_in,
                              void* d_out, int out_size)
{
    const float* hidden = (const float*)d_in[0];
    const float* w_attn = (const float*)d_in[1];
    const float* b_attn = (const float*)d_in[2];
    const float* w_proj = (const float*)d_in[3];
    const float* b_proj = (const float*)d_in[4];
    float* out = (float*)d_out;

    float* qkv = nullptr;
    float* att = nullptr;
    float* wT  = nullptr;
    cudaGetSymbolAddress((void**)&qkv, g_qkv);
    cudaGetSymbolAddress((void**)&att, g_att);
    cudaGetSymbolAddress((void**)&wT,  g_wT);
    float* wTa = wT;                                   // [3072][1024]
    float* wTp = wT + (size_t)QKV_N * DMODEL;          // [1024][1024]

    cudaFuncSetAttribute(gemm_tc, cudaFuncAttributeMaxDynamicSharedMemorySize,
                         GEMM_DYN_SMEM);
    cudaFuncSetAttribute(attn_tc, cudaFuncAttributeMaxDynamicSharedMemorySize,
                         ATTN_SMEM);

    // 0) Transpose weights to [N][K]
    {
        dim3 blk(32, 8);
        transpose_kernel<<<dim3(QKV_N / 32, DMODEL / 32), blk>>>(w_attn, wTa, DMODEL, QKV_N);
        transpose_kernel<<<dim3(DMODEL / 32, DMODEL / 32), blk>>>(w_proj, wTp, DMODEL, DMODEL);
    }

    // 1) QKV projection (3xtf32 mma): [4096,1024] @ [1024,3072] + bias
    {
        dim3 grid(QKV_N / 128, M_ROWS / 128);
        gemm_tc<<<grid, 256, GEMM_DYN_SMEM>>>(hidden, wTa, b_attn, qkv,
                                              M_ROWS, QKV_N, DMODEL);
    }

    // 2) Causal attention (3xtf32 mma flash attention)
    {
        dim3 grid(BATCH * NHEAD, SEQ / TQ);
        attn_tc<<<grid, 256, ATTN_SMEM>>>(qkv, att);
    }

    // 3) Output projection (3xtf32 mma): [4096,1024] @ [1024,1024] + bias
    {
        dim3 grid(DMODEL / 128, M_ROWS / 128);
        gemm_tc<<<grid, 256, GEMM_DYN_SMEM>>>(att, wTp, b_proj, out,
                                              M_ROWS, DMODEL, DMODEL);
    }
}

// round 7
// speedup vs baseline: 1.7110x; 1.0623x over previous
#include <cuda_runtime.h>
#include <cuda_bf16.h>
#include <cstdint>
#include <math.h>

// Problem constants
#define BATCH 2
#define SEQ   2048
#define DMODEL 1024
#define NHEAD 16
#define HD    64
#define M_ROWS (BATCH*SEQ)        // 4096
#define QKV_N  (3*DMODEL)         // 3072

// Scratch (device globals; allocation is forbidden)
__device__ float g_qkv[(size_t)M_ROWS * QKV_N];                        // 48 MB
__device__ float g_att[(size_t)M_ROWS * DMODEL];                       // 16 MB
__device__ float g_wT[(size_t)QKV_N * DMODEL + (size_t)DMODEL*DMODEL]; // 16 MB

// ===========================================================================
// PTX helpers
// ===========================================================================
__device__ __forceinline__ uint32_t smem_u32(const void* p) {
    uint32_t a;
    asm("{ .reg .u64 t; cvta.to.shared.u64 t, %1; cvt.u32.u64 %0, t; }"
        : "=r"(a) : "l"(p));
    return a;
}
__device__ __forceinline__ void cp_async16(uint32_t s, const void* g) {
    asm volatile("cp.async.cg.shared.global [%0], [%1], 16;" :: "r"(s), "l"(g));
}
__device__ __forceinline__ void cp_commit() {
    asm volatile("cp.async.commit_group;" ::: "memory");
}
template<int N> __device__ __forceinline__ void cp_wait() {
    asm volatile("cp.async.wait_group %0;" :: "n"(N) : "memory");
}

// tf32 mma: D[16x8] += A[16x8] * B[8x8]  (row.col)
__device__ __forceinline__ void mma_tf32(float* c, const uint32_t* a, const uint32_t* b) {
    asm volatile(
        "mma.sync.aligned.m16n8k8.row.col.f32.tf32.tf32.f32 "
        "{%0,%1,%2,%3}, {%4,%5,%6,%7}, {%8,%9}, {%0,%1,%2,%3};"
        : "+f"(c[0]), "+f"(c[1]), "+f"(c[2]), "+f"(c[3])
        : "r"(a[0]), "r"(a[1]), "r"(a[2]), "r"(a[3]), "r"(b[0]), "r"(b[1]));
}

// Split fp32 into hi (tf32-truncated) + lo (residual) for 3xTF32
__device__ __forceinline__ void tf32_split(uint32_t x, uint32_t& hi, uint32_t& lo) {
    hi = x & 0xFFFFE000u;
    lo = __float_as_uint(__uint_as_float(x) - __uint_as_float(hi));
}

// ===========================================================================
// Weight transpose: out[c][r] = in[r][c]   (in: [R][C])
// ===========================================================================
__global__ void transpose_kernel(const float* __restrict__ in, float* __restrict__ out,
                                 int R, int C) {
    __shared__ float t[32][33];
    int c0 = blockIdx.x * 32, r0 = blockIdx.y * 32;
    int tx = threadIdx.x, ty = threadIdx.y;   // 32 x 8
#pragma unroll
    for (int i = 0; i < 32; i += 8)
        t[ty + i][tx] = in[(size_t)(r0 + ty + i) * C + c0 + tx];
    __syncthreads();
#pragma unroll
    for (int i = 0; i < 32; i += 8)
        out[(size_t)(c0 + ty + i) * R + r0 + tx] = t[tx][ty + i];
}

// ===========================================================================
// 3xTF32 mma.sync GEMM: C[M,N] = A[M,K] @ BT[N,K]^T + bias[N]
// CTA tile 128(M) x 256(N), 256 threads (8 warps, warp tile 64x64), BK=32,
// 2-stage cp.async pipeline. Full 3-term: acc += ah*bh + al*bh + ah*bl.
// ===========================================================================
#define BK 32
#define SROW 36
#define A_FLOATS (128 * SROW)
#define B_FLOATS (256 * SROW)
#define STAGE_FLOATS (A_FLOATS + B_FLOATS)           // 13824
#define GEMM_DYN_SMEM (2 * STAGE_FLOATS * 4)         // 110592 B

__global__ __launch_bounds__(256, 1) void gemm_tc(
    const float* __restrict__ A, const float* __restrict__ BT,
    const float* __restrict__ bias, float* __restrict__ C,
    int M, int N, int K)
{
    extern __shared__ float smem[];
    const int tid = threadIdx.x;
    const int wid = tid >> 5, lid = tid & 31;
    const int g = lid >> 2, t = lid & 3;
    const int warp_m = (wid & 1) * 64;         // 2 m-warps
    const int warp_n = (wid >> 1) * 64;        // 4 n-warps
    const int row0 = blockIdx.y * 128;
    const int col0 = blockIdx.x * 256;

    const uint32_t sb = smem_u32(smem);
    const float* Abase  = A  + (size_t)row0 * K;
    const float* BTbase = BT + (size_t)col0 * K;
    const int NC = K / BK;                     // 32

    auto load_chunk = [&](int c, int s) {
        const float* Ag = Abase  + c * BK;
        const float* Bg = BTbase + c * BK;
        uint32_t abase = sb + (uint32_t)(s * STAGE_FLOATS) * 4;
        uint32_t bbase = abase + A_FLOATS * 4;
#pragma unroll
        for (int i = 0; i < 4; i++) {          // A: 128 rows x 8 chunks
            int idx = i * 256 + tid;
            int r = idx >> 3, q = idx & 7;
            cp_async16(abase + (uint32_t)(r * SROW + q * 4) * 4,
                       Ag + (size_t)r * K + q * 4);
        }
#pragma unroll
        for (int i = 0; i < 8; i++) {          // B: 256 rows x 8 chunks
            int idx = i * 256 + tid;
            int r = idx >> 3, q = idx & 7;
            cp_async16(bbase + (uint32_t)(r * SROW + q * 4) * 4,
                       Bg + (size_t)r * K + q * 4);
        }
        cp_commit();
    };

    load_chunk(0, 0);
    load_chunk(1, 1);

    float acc[4][8][4];
#pragma unroll
    for (int mt = 0; mt < 4; mt++)
#pragma unroll
        for (int nt = 0; nt < 8; nt++)
#pragma unroll
            for (int r = 0; r < 4; r++) acc[mt][nt][r] = 0.f;

    int s = 0;
    for (int c = 0; c < NC; c++) {
        cp_wait<1>();
        __syncthreads();

        const uint32_t* As = (const uint32_t*)(smem + s * STAGE_FLOATS);
        const uint32_t* Bs = As + A_FLOATS;

#pragma unroll
        for (int kk = 0; kk < BK / 8; kk++) {
            const int kc = kk * 8;
            uint32_t ah[4][4], al[4][4];
#pragma unroll
            for (int mt = 0; mt < 4; mt++) {
                int r0 = warp_m + mt * 16 + g;
                uint32_t raw[4];
                raw[0] = As[r0 * SROW + kc + t];
                raw[1] = As[(r0 + 8) * SROW + kc + t];
                raw[2] = As[r0 * SROW + kc + t + 4];
                raw[3] = As[(r0 + 8) * SROW + kc + t + 4];
#pragma unroll
                for (int r = 0; r < 4; r++)
                    tf32_split(raw[r], ah[mt][r], al[mt][r]);
            }
#pragma unroll
            for (int nt = 0; nt < 8; nt++) {
                int n0 = warp_n + nt * 8 + g;
                uint32_t braw[2], bh[2], bl[2];
                braw[0] = Bs[n0 * SROW + kc + t];
                braw[1] = Bs[n0 * SROW + kc + t + 4];
                tf32_split(braw[0], bh[0], bl[0]);
                tf32_split(braw[1], bh[1], bl[1]);
#pragma unroll
                for (int mt = 0; mt < 4; mt++) {
                    mma_tf32(acc[mt][nt], ah[mt], bh);
                    mma_tf32(acc[mt][nt], al[mt], bh);
                    mma_tf32(acc[mt][nt], ah[mt], bl);
                }
            }
        }

        __syncthreads();
        if (c + 2 < NC) load_chunk(c + 2, s);
        else            cp_commit();           // keep group counting aligned
        s ^= 1;
    }

    // ---- epilogue ----
#pragma unroll
    for (int mt = 0; mt < 4; mt++) {
        int r0 = row0 + warp_m + mt * 16 + g;
#pragma unroll
        for (int nt = 0; nt < 8; nt++) {
            int gc = col0 + warp_n + nt * 8 + 2 * t;
            float b0 = bias[gc], b1 = bias[gc + 1];
            float2 v0 = make_float2(acc[mt][nt][0] + b0, acc[mt][nt][1] + b1);
            float2 v1 = make_float2(acc[mt][nt][2] + b0, acc[mt][nt][3] + b1);
            *(float2*)&C[(size_t)r0 * N + gc] = v0;
            *(float2*)&C[(size_t)(r0 + 8) * N + gc] = v1;
        }
    }
}

// ===========================================================================
// Tensor-core causal flash attention (3xTF32 mma.sync), 2 CTAs/SM.
// ===========================================================================
#define TQ 128
#define TK 64
#define PADQ 68
#define PADK 68
#define PADV 72
#define PADP 68
#define ATTN_SMEM ((TQ*PADQ + TK*PADK + TK*PADV + 8*16*PADP) * 4)  // 105472 B

__global__ __launch_bounds__(256, 2) void attn_tc(
    const float* __restrict__ qkv, float* __restrict__ out)
{
    extern __shared__ float sm[];
    float* Qs = sm;                          // [128][PADQ]
    float* Ks = Qs + TQ * PADQ;              // [64][PADK]
    float* Vs = Ks + TK * PADK;              // [64][PADV]
    float* Ps = Vs + TK * PADV;              // per warp [16][PADP]

    const int bh = blockIdx.x;
    const int b  = bh >> 4;
    const int h  = bh & 15;
    const int qt = (gridDim.y - 1) - blockIdx.y;   // heavy tiles first
    const int q0 = qt * TQ;

    const int tid = threadIdx.x;
    const int wid = tid >> 5, lid = tid & 31;
    const int g = lid >> 2, t = lid & 3;
    const int wm = wid * 16;
    float* Pw = Ps + wid * 16 * PADP;

    const float* base = qkv + (size_t)(b * SEQ) * QKV_N + h * HD;

    for (int idx = tid; idx < TQ * 16; idx += 256) {
        int r = idx >> 4, q = idx & 15;
        *(float4*)&Qs[r * PADQ + q * 4] =
            *(const float4*)&base[(size_t)(q0 + r) * QKV_N + q * 4];
    }

    float m_i[2] = {-1e30f, -1e30f};
    float l_i[2] = {0.f, 0.f};
    float oacc[8][4];
#pragma unroll
    for (int nt = 0; nt < 8; nt++)
#pragma unroll
        for (int r = 0; r < 4; r++) oacc[nt][r] = 0.f;

    const int nkt = 2 * qt + 2;
    for (int kt = 0; kt < nkt; kt++) {
        const int k0 = kt * TK;
        __syncthreads();
        for (int idx = tid; idx < TK * 16; idx += 256) {
            int r = idx >> 4, q = idx & 15;
            size_t gofs = (size_t)(k0 + r) * QKV_N + q * 4;
            *(float4*)&Ks[r * PADK + q * 4] = *(const float4*)&base[DMODEL + gofs];
            *(float4*)&Vs[r * PADV + q * 4] = *(const float4*)&base[2 * DMODEL + gofs];
        }
        __syncthreads();

        if (k0 > q0 + wm + 15) continue;

        float sacc[8][4];
#pragma unroll
        for (int nt = 0; nt < 8; nt++)
#pragma unroll
            for (int r = 0; r < 4; r++) sacc[nt][r] = 0.f;

#pragma unroll
        for (int kc8 = 0; kc8 < 8; kc8++) {
            const int kc = kc8 * 8;
            uint32_t araw[4], ah[4], al[4];
            araw[0] = __float_as_uint(Qs[(wm + g)     * PADQ + kc + t]);
            araw[1] = __float_as_uint(Qs[(wm + g + 8) * PADQ + kc + t]);
            araw[2] = __float_as_uint(Qs[(wm + g)     * PADQ + kc + t + 4]);
            araw[3] = __float_as_uint(Qs[(wm + g + 8) * PADQ + kc + t + 4]);
#pragma unroll
            for (int r = 0; r < 4; r++) tf32_split(araw[r], ah[r], al[r]);
#pragma unroll
            for (int nt = 0; nt < 8; nt++) {
                uint32_t braw[2], bh[2], bl[2];
                braw[0] = __float_as_uint(Ks[(nt * 8 + g) * PADK + kc + t]);
                braw[1] = __float_as_uint(Ks[(nt * 8 + g) * PADK + kc + t + 4]);
                tf32_split(braw[0], bh[0], bl[0]);
                tf32_split(braw[1], bh[1], bl[1]);
                mma_tf32(sacc[nt], ah, bh);
                mma_tf32(sacc[nt], al, bh);
                mma_tf32(sacc[nt], ah, bl);
            }
        }

        if (k0 + TK - 1 > q0 + wm) {
            const int r0g = q0 + wm + g;
#pragma unroll
            for (int nt = 0; nt < 8; nt++) {
                int c0 = k0 + nt * 8 + 2 * t;
                if (c0     > r0g)     sacc[nt][0] = -1e30f;
                if (c0 + 1 > r0g)     sacc[nt][1] = -1e30f;
                if (c0     > r0g + 8) sacc[nt][2] = -1e30f;
                if (c0 + 1 > r0g + 8) sacc[nt][3] = -1e30f;
            }
        }

        float rm[2];
        rm[0] = fmaxf(sacc[0][0], sacc[0][1]);
        rm[1] = fmaxf(sacc[0][2], sacc[0][3]);
#pragma unroll
        for (int nt = 1; nt < 8; nt++) {
            rm[0] = fmaxf(rm[0], fmaxf(sacc[nt][0], sacc[nt][1]));
            rm[1] = fmaxf(rm[1], fmaxf(sacc[nt][2], sacc[nt][3]));
        }
#pragma unroll
        for (int off = 1; off < 4; off <<= 1) {
            rm[0] = fmaxf(rm[0], __shfl_xor_sync(0xffffffffu, rm[0], off));
            rm[1] = fmaxf(rm[1], __shfl_xor_sync(0xffffffffu, rm[1], off));
        }
        float mn0 = fmaxf(m_i[0], rm[0]), mn1 = fmaxf(m_i[1], rm[1]);
        float sc0 = __expf(m_i[0] - mn0), sc1 = __expf(m_i[1] - mn1);
        float rs0 = 0.f, rs1 = 0.f;
#pragma unroll
        for (int nt = 0; nt < 8; nt++) {
            sacc[nt][0] = __expf(sacc[nt][0] - mn0); rs0 += sacc[nt][0];
            sacc[nt][1] = __expf(sacc[nt][1] - mn0); rs0 += sacc[nt][1];
            sacc[nt][2] = __expf(sacc[nt][2] - mn1); rs1 += sacc[nt][2];
            sacc[nt][3] = __expf(sacc[nt][3] - mn1); rs1 += sacc[nt][3];
        }
#pragma unroll
        for (int off = 1; off < 4; off <<= 1) {
            rs0 += __shfl_xor_sync(0xffffffffu, rs0, off);
            rs1 += __shfl_xor_sync(0xffffffffu, rs1, off);
        }
        l_i[0] = l_i[0] * sc0 + rs0;  m_i[0] = mn0;
        l_i[1] = l_i[1] * sc1 + rs1;  m_i[1] = mn1;
#pragma unroll
        for (int nt = 0; nt < 8; nt++) {
            oacc[nt][0] *= sc0; oacc[nt][1] *= sc0;
            oacc[nt][2] *= sc1; oacc[nt][3] *= sc1;
        }

#pragma unroll
        for (int nt = 0; nt < 8; nt++) {
            *(float2*)&Pw[g       * PADP + nt * 8 + 2 * t] = make_float2(sacc[nt][0], sacc[nt][1]);
            *(float2*)&Pw[(g + 8) * PADP + nt * 8 + 2 * t] = make_float2(sacc[nt][2], sacc[nt][3]);
        }
        __syncwarp();

#pragma unroll
        for (int kc8 = 0; kc8 < 8; kc8++) {
            const int kc = kc8 * 8;
            uint32_t araw[4], ah[4], al[4];
            araw[0] = __float_as_uint(Pw[g       * PADP + kc + t]);
            araw[1] = __float_as_uint(Pw[(g + 8) * PADP + kc + t]);
            araw[2] = __float_as_uint(Pw[g       * PADP + kc + t + 4]);
            araw[3] = __float_as_uint(Pw[(g + 8) * PADP + kc + t + 4]);
#pragma unroll
            for (int r = 0; r < 4; r++) tf32_split(araw[r], ah[r], al[r]);
#pragma unroll
            for (int nt = 0; nt < 8; nt++) {
                uint32_t braw[2], bh[2], bl[2];
                braw[0] = __float_as_uint(Vs[(kc + t)     * PADV + nt * 8 + g]);
                braw[1] = __float_as_uint(Vs[(kc + t + 4) * PADV + nt * 8 + g]);
                tf32_split(braw[0], bh[0], bl[0]);
                tf32_split(braw[1], bh[1], bl[1]);
                mma_tf32(oacc[nt], ah, bh);
                mma_tf32(oacc[nt], al, bh);
                mma_tf32(oacc[nt], ah, bl);
            }
        }
        __syncwarp();
    }

    const float inv0 = 1.f / l_i[0], inv1 = 1.f / l_i[1];
    const size_t gr0 = (size_t)(b * SEQ + q0 + wm + g);
    float* ob = out + h * HD;
#pragma unroll
    for (int nt = 0; nt < 8; nt++) {
        int gc = nt * 8 + 2 * t;
        *(float2*)&ob[gr0 * DMODEL + gc] =
            make_float2(oacc[nt][0] * inv0, oacc[nt][1] * inv0);
        *(float2*)&ob[(gr0 + 8) * DMODEL + gc] =
            make_float2(oacc[nt][2] * inv1, oacc[nt][3] * inv1);
    }
}

// ===========================================================================
extern "C" void kernel_launch(void* const* d_in, const int* in_sizes, int n_in,
                              void* d_out, int out_size)
{
    const float* hidden = (const float*)d_in[0];
    const float* w_attn = (const float*)d_in[1];
    const float* b_attn = (const float*)d_in[2];
    const float* w_proj = (const float*)d_in[3];
    const float* b_proj = (const float*)d_in[4];
    float* out = (float*)d_out;

    float* qkv = nullptr;
    float* att = nullptr;
    float* wT  = nullptr;
    cudaGetSymbolAddress((void**)&qkv, g_qkv);
    cudaGetSymbolAddress((void**)&att, g_att);
    cudaGetSymbolAddress((void**)&wT,  g_wT);
    float* wTa = wT;                                   // [3072][1024]
    float* wTp = wT + (size_t)QKV_N * DMODEL;          // [1024][1024]

    cudaFuncSetAttribute(gemm_tc, cudaFuncAttributeMaxDynamicSharedMemorySize,
                         GEMM_DYN_SMEM);
    cudaFuncSetAttribute(attn_tc, cudaFuncAttributeMaxDynamicSharedMemorySize,
                         ATTN_SMEM);

    // 0) Transpose weights to [N][K]
    {
        dim3 blk(32, 8);
        transpose_kernel<<<dim3(QKV_N / 32, DMODEL / 32), blk>>>(w_attn, wTa, DMODEL, QKV_N);
        transpose_kernel<<<dim3(DMODEL / 32, DMODEL / 32), blk>>>(w_proj, wTp, DMODEL, DMODEL);
    }

    // 1) QKV projection (3xtf32 mma, 128x256 tile): [4096,1024] @ [1024,3072] + bias
    {
        dim3 grid(QKV_N / 256, M_ROWS / 128);
        gemm_tc<<<grid, 256, GEMM_DYN_SMEM>>>(hidden, wTa, b_attn, qkv,
                                              M_ROWS, QKV_N, DMODEL);
    }

    // 2) Causal attention (3xtf32 mma flash attention, 2 CTAs/SM)
    {
        dim3 grid(BATCH * NHEAD, SEQ / TQ);
        attn_tc<<<grid, 256, ATTN_SMEM>>>(qkv, att);
    }

    // 3) Output projection (3xtf32 mma, 128x256 tile): [4096,1024] @ [1024,1024] + bias
    {
        dim3 grid(DMODEL / 256, M_ROWS / 128);
        gemm_tc<<<grid, 256, GEMM_DYN_SMEM>>>(att, wTp, b_proj, out,
                                              M_ROWS, DMODEL, DMODEL);
    }
}

// round 8
// speedup vs baseline: 2.2324x; 1.3047x over previous
#include <cuda_runtime.h>
#include <cuda_bf16.h>
#include <cstdint>
#include <math.h>

// Problem constants
#define BATCH 2
#define SEQ   2048
#define DMODEL 1024
#define NHEAD 16
#define HD    64
#define M_ROWS (BATCH*SEQ)        // 4096
#define QKV_N  (3*DMODEL)         // 3072

// Scratch (device globals; allocation is forbidden)
__device__ float g_qkv[(size_t)M_ROWS * QKV_N];    // 48 MB
__device__ float g_att[(size_t)M_ROWS * DMODEL];   // 16 MB
// bf16 hi/lo packed operands
__device__ __nv_bfloat16 g_wTh[(size_t)(QKV_N + DMODEL) * DMODEL];  // 8 MB
__device__ __nv_bfloat16 g_wTl[(size_t)(QKV_N + DMODEL) * DMODEL];  // 8 MB
__device__ __nv_bfloat16 g_xh[(size_t)M_ROWS * DMODEL];             // 8 MB
__device__ __nv_bfloat16 g_xl[(size_t)M_ROWS * DMODEL];             // 8 MB

// ===========================================================================
// PTX helpers
// ===========================================================================
__device__ __forceinline__ uint32_t smem_u32(const void* p) {
    uint32_t a;
    asm("{ .reg .u64 t; cvta.to.shared.u64 t, %1; cvt.u32.u64 %0, t; }"
        : "=r"(a) : "l"(p));
    return a;
}
__device__ __forceinline__ void cp_async16(uint32_t s, const void* g) {
    asm volatile("cp.async.cg.shared.global [%0], [%1], 16;" :: "r"(s), "l"(g));
}
__device__ __forceinline__ void cp_commit() {
    asm volatile("cp.async.commit_group;" ::: "memory");
}
template<int N> __device__ __forceinline__ void cp_wait() {
    asm volatile("cp.async.wait_group %0;" :: "n"(N) : "memory");
}

// tf32 mma: D[16x8] += A[16x8] * B[8x8]  (row.col)  -- used by attention
__device__ __forceinline__ void mma_tf32(float* c, const uint32_t* a, const uint32_t* b) {
    asm volatile(
        "mma.sync.aligned.m16n8k8.row.col.f32.tf32.tf32.f32 "
        "{%0,%1,%2,%3}, {%4,%5,%6,%7}, {%8,%9}, {%0,%1,%2,%3};"
        : "+f"(c[0]), "+f"(c[1]), "+f"(c[2]), "+f"(c[3])
        : "r"(a[0]), "r"(a[1]), "r"(a[2]), "r"(a[3]), "r"(b[0]), "r"(b[1]));
}

// bf16 mma: D[16x8] += A[16x16] * B[16x8]  (row.col)
__device__ __forceinline__ void mma_bf16(float* c, const uint32_t* a, const uint32_t* b) {
    asm volatile(
        "mma.sync.aligned.m16n8k16.row.col.f32.bf16.bf16.f32 "
        "{%0,%1,%2,%3}, {%4,%5,%6,%7}, {%8,%9}, {%0,%1,%2,%3};"
        : "+f"(c[0]), "+f"(c[1]), "+f"(c[2]), "+f"(c[3])
        : "r"(a[0]), "r"(a[1]), "r"(a[2]), "r"(a[3]), "r"(b[0]), "r"(b[1]));
}

// tf32 split (attention only)
__device__ __forceinline__ void tf32_split(uint32_t x, uint32_t& hi, uint32_t& lo) {
    hi = x & 0xFFFFE000u;
    lo = __float_as_uint(__uint_as_float(x) - __uint_as_float(hi));
}

// ===========================================================================
// Pre-pass: elementwise split fp32 -> packed bf16 hi/lo
// ===========================================================================
__global__ void split_pack(const float* __restrict__ in,
                           __nv_bfloat16* __restrict__ hi,
                           __nv_bfloat16* __restrict__ lo, int n4)
{
    int i = blockIdx.x * blockDim.x + threadIdx.x;
    if (i >= n4) return;
    float4 v = *(const float4*)(in + (size_t)i * 4);
    uint32_t h0, h1, l0, l1;
    asm("cvt.rn.bf16x2.f32 %0, %1, %2;" : "=r"(h0) : "f"(v.y), "f"(v.x));
    asm("cvt.rn.bf16x2.f32 %0, %1, %2;" : "=r"(h1) : "f"(v.w), "f"(v.z));
    float r0 = v.x - __uint_as_float(h0 << 16);
    float r1 = v.y - __uint_as_float(h0 & 0xFFFF0000u);
    float r2 = v.z - __uint_as_float(h1 << 16);
    float r3 = v.w - __uint_as_float(h1 & 0xFFFF0000u);
    asm("cvt.rn.bf16x2.f32 %0, %1, %2;" : "=r"(l0) : "f"(r1), "f"(r0));
    asm("cvt.rn.bf16x2.f32 %0, %1, %2;" : "=r"(l1) : "f"(r3), "f"(r2));
    ((uint2*)hi)[i] = make_uint2(h0, h1);
    ((uint2*)lo)[i] = make_uint2(l0, l1);
}

// ===========================================================================
// Pre-pass: transpose + split: in [R][C] fp32 -> outHi/outLo [C][R] bf16
// ===========================================================================
__global__ void transpose_split(const float* __restrict__ in,
                                __nv_bfloat16* __restrict__ outH,
                                __nv_bfloat16* __restrict__ outL, int R, int C)
{
    __shared__ float t[32][33];
    int c0 = blockIdx.x * 32, r0 = blockIdx.y * 32;
    int tx = threadIdx.x, ty = threadIdx.y;   // 32 x 8
#pragma unroll
    for (int i = 0; i < 32; i += 8)
        t[ty + i][tx] = in[(size_t)(r0 + ty + i) * C + c0 + tx];
    __syncthreads();
#pragma unroll
    for (int i = 0; i < 32; i += 8) {
        float v = t[tx][ty + i];
        __nv_bfloat16 h = __float2bfloat16(v);
        float lof = v - __bfloat162float(h);
        size_t o = (size_t)(c0 + ty + i) * R + r0 + tx;
        outH[o] = h;
        outL[o] = __float2bfloat16(lof);
    }
}

// ===========================================================================
// 3xBF16 mma.sync GEMM: C[M,N] = A[M,K] @ BT[N,K]^T + bias[N]
// Operands pre-split into packed bf16 hi/lo ([row][K/2] uint32 words).
// CTA tile 128(M) x 256(N), 256 threads (8 warps, warp tile 64x64), BK=32,
// 2-stage cp.async pipeline.  acc += ah*bh + al*bh + ah*bl.
// smem row stride SA=20 words (16 + 4 pad) -> conflict-free frag loads.
// ===========================================================================
#define SA 20
#define AW (128 * SA)                  // 2560 words per A tile
#define BW (256 * SA)                  // 5120 words per B tile
#define STAGE_WORDS (2*AW + 2*BW)      // Ah, Al, Bh, Bl = 15360 words
#define GEMM_DYN_SMEM (2 * STAGE_WORDS * 4)   // 122880 B

__global__ __launch_bounds__(256, 1) void gemm_bf3(
    const __nv_bfloat16* __restrict__ Ah_, const __nv_bfloat16* __restrict__ Al_,
    const __nv_bfloat16* __restrict__ Bh_, const __nv_bfloat16* __restrict__ Bl_,
    const float* __restrict__ bias, float* __restrict__ C,
    int M, int N, int K)
{
    extern __shared__ uint32_t smw[];
    const int tid = threadIdx.x;
    const int wid = tid >> 5, lid = tid & 31;
    const int g = lid >> 2, t4 = lid & 3;
    const int warp_m = (wid & 1) * 64;
    const int warp_n = (wid >> 1) * 64;
    const int row0 = blockIdx.y * 128;
    const int col0 = blockIdx.x * 256;

    const uint32_t sb = smem_u32(smw);
    const int KW = K >> 1;                       // words per gmem row
    const uint32_t* AwH = (const uint32_t*)Ah_ + (size_t)row0 * KW;
    const uint32_t* AwL = (const uint32_t*)Al_ + (size_t)row0 * KW;
    const uint32_t* BwH = (const uint32_t*)Bh_ + (size_t)col0 * KW;
    const uint32_t* BwL = (const uint32_t*)Bl_ + (size_t)col0 * KW;
    const int NC = K / 32;                       // chunks (16 words each)

    auto load_chunk = [&](int c, int s) {
        const int kw = c * 16;
        uint32_t st = sb + (uint32_t)(s * STAGE_WORDS) * 4;
#pragma unroll
        for (int i = 0; i < 2; i++) {            // A: 128 rows x 4 cp each tile
            int idx = i * 256 + tid;             // 0..511
            int r = idx >> 2, q = idx & 3;
            uint32_t off = (uint32_t)(r * SA + q * 4) * 4;
            const uint32_t* srcH = AwH + (size_t)r * KW + kw + q * 4;
            const uint32_t* srcL = AwL + (size_t)r * KW + kw + q * 4;
            cp_async16(st + off, srcH);
            cp_async16(st + AW * 4 + off, srcL);
        }
#pragma unroll
        for (int i = 0; i < 4; i++) {            // B: 256 rows
            int idx = i * 256 + tid;             // 0..1023
            int r = idx >> 2, q = idx & 3;
            uint32_t off = (uint32_t)(r * SA + q * 4) * 4;
            const uint32_t* srcH = BwH + (size_t)r * KW + kw + q * 4;
            const uint32_t* srcL = BwL + (size_t)r * KW + kw + q * 4;
            cp_async16(st + 2 * AW * 4 + off, srcH);
            cp_async16(st + (2 * AW + BW) * 4 + off, srcL);
        }
        cp_commit();
    };

    load_chunk(0, 0);
    load_chunk(1, 1);

    float acc[4][8][4];
#pragma unroll
    for (int mt = 0; mt < 4; mt++)
#pragma unroll
        for (int nt = 0; nt < 8; nt++)
#pragma unroll
            for (int r = 0; r < 4; r++) acc[mt][nt][r] = 0.f;

    int s = 0;
    for (int c = 0; c < NC; c++) {
        cp_wait<1>();
        __syncthreads();

        const uint32_t* AH = smw + s * STAGE_WORDS;
        const uint32_t* AL = AH + AW;
        const uint32_t* BH = AL + AW;
        const uint32_t* BL = BH + BW;

#pragma unroll
        for (int kk = 0; kk < 2; kk++) {         // two k16 slices per chunk
            const int kw = kk * 8;
            uint32_t ah[4][4], al[4][4];
#pragma unroll
            for (int mt = 0; mt < 4; mt++) {
                int base = (warp_m + mt * 16 + g) * SA + kw + t4;
                ah[mt][0] = AH[base];
                ah[mt][1] = AH[base + 8 * SA];
                ah[mt][2] = AH[base + 4];
                ah[mt][3] = AH[base + 8 * SA + 4];
                al[mt][0] = AL[base];
                al[mt][1] = AL[base + 8 * SA];
                al[mt][2] = AL[base + 4];
                al[mt][3] = AL[base + 8 * SA + 4];
            }
#pragma unroll
            for (int nt = 0; nt < 8; nt++) {
                int nb = (warp_n + nt * 8 + g) * SA + kw + t4;
                uint32_t bh[2], bl[2];
                bh[0] = BH[nb]; bh[1] = BH[nb + 4];
                bl[0] = BL[nb]; bl[1] = BL[nb + 4];
#pragma unroll
                for (int mt = 0; mt < 4; mt++) {
                    mma_bf16(acc[mt][nt], ah[mt], bh);
                    mma_bf16(acc[mt][nt], al[mt], bh);
                    mma_bf16(acc[mt][nt], ah[mt], bl);
                }
            }
        }

        __syncthreads();
        if (c + 2 < NC) load_chunk(c + 2, s);
        else            cp_commit();
        s ^= 1;
    }

    // ---- epilogue: + bias, fp32 out ----
#pragma unroll
    for (int mt = 0; mt < 4; mt++) {
        int r0 = row0 + warp_m + mt * 16 + g;
#pragma unroll
        for (int nt = 0; nt < 8; nt++) {
            int gc = col0 + warp_n + nt * 8 + 2 * t4;
            float b0 = bias[gc], b1 = bias[gc + 1];
            float2 v0 = make_float2(acc[mt][nt][0] + b0, acc[mt][nt][1] + b1);
            float2 v1 = make_float2(acc[mt][nt][2] + b0, acc[mt][nt][3] + b1);
            *(float2*)&C[(size_t)r0 * N + gc] = v0;
            *(float2*)&C[(size_t)(r0 + 8) * N + gc] = v1;
        }
    }
}

// ===========================================================================
// Tensor-core causal flash attention (3xTF32 mma.sync), 2 CTAs/SM. Unchanged.
// ===========================================================================
#define TQ 128
#define TK 64
#define PADQ 68
#define PADK 68
#define PADV 72
#define PADP 68
#define ATTN_SMEM ((TQ*PADQ + TK*PADK + TK*PADV + 8*16*PADP) * 4)  // 105472 B

__global__ __launch_bounds__(256, 2) void attn_tc(
    const float* __restrict__ qkv, float* __restrict__ out)
{
    extern __shared__ float sm[];
    float* Qs = sm;
    float* Ks = Qs + TQ * PADQ;
    float* Vs = Ks + TK * PADK;
    float* Ps = Vs + TK * PADV;

    const int bh = blockIdx.x;
    const int b  = bh >> 4;
    const int h  = bh & 15;
    const int qt = (gridDim.y - 1) - blockIdx.y;
    const int q0 = qt * TQ;

    const int tid = threadIdx.x;
    const int wid = tid >> 5, lid = tid & 31;
    const int g = lid >> 2, t = lid & 3;
    const int wm = wid * 16;
    float* Pw = Ps + wid * 16 * PADP;

    const float* base = qkv + (size_t)(b * SEQ) * QKV_N + h * HD;

    for (int idx = tid; idx < TQ * 16; idx += 256) {
        int r = idx >> 4, q = idx & 15;
        *(float4*)&Qs[r * PADQ + q * 4] =
            *(const float4*)&base[(size_t)(q0 + r) * QKV_N + q * 4];
    }

    float m_i[2] = {-1e30f, -1e30f};
    float l_i[2] = {0.f, 0.f};
    float oacc[8][4];
#pragma unroll
    for (int nt = 0; nt < 8; nt++)
#pragma unroll
        for (int r = 0; r < 4; r++) oacc[nt][r] = 0.f;

    const int nkt = 2 * qt + 2;
    for (int kt = 0; kt < nkt; kt++) {
        const int k0 = kt * TK;
        __syncthreads();
        for (int idx = tid; idx < TK * 16; idx += 256) {
            int r = idx >> 4, q = idx & 15;
            size_t gofs = (size_t)(k0 + r) * QKV_N + q * 4;
            *(float4*)&Ks[r * PADK + q * 4] = *(const float4*)&base[DMODEL + gofs];
            *(float4*)&Vs[r * PADV + q * 4] = *(const float4*)&base[2 * DMODEL + gofs];
        }
        __syncthreads();

        if (k0 > q0 + wm + 15) continue;

        float sacc[8][4];
#pragma unroll
        for (int nt = 0; nt < 8; nt++)
#pragma unroll
            for (int r = 0; r < 4; r++) sacc[nt][r] = 0.f;

#pragma unroll
        for (int kc8 = 0; kc8 < 8; kc8++) {
            const int kc = kc8 * 8;
            uint32_t araw[4], ah[4], al[4];
            araw[0] = __float_as_uint(Qs[(wm + g)     * PADQ + kc + t]);
            araw[1] = __float_as_uint(Qs[(wm + g + 8) * PADQ + kc + t]);
            araw[2] = __float_as_uint(Qs[(wm + g)     * PADQ + kc + t + 4]);
            araw[3] = __float_as_uint(Qs[(wm + g + 8) * PADQ + kc + t + 4]);
#pragma unroll
            for (int r = 0; r < 4; r++) tf32_split(araw[r], ah[r], al[r]);
#pragma unroll
            for (int nt = 0; nt < 8; nt++) {
                uint32_t braw[2], bh[2], bl[2];
                braw[0] = __float_as_uint(Ks[(nt * 8 + g) * PADK + kc + t]);
                braw[1] = __float_as_uint(Ks[(nt * 8 + g) * PADK + kc + t + 4]);
                tf32_split(braw[0], bh[0], bl[0]);
                tf32_split(braw[1], bh[1], bl[1]);
                mma_tf32(sacc[nt], ah, bh);
                mma_tf32(sacc[nt], al, bh);
                mma_tf32(sacc[nt], ah, bl);
            }
        }

        if (k0 + TK - 1 > q0 + wm) {
            const int r0g = q0 + wm + g;
#pragma unroll
            for (int nt = 0; nt < 8; nt++) {
                int c0 = k0 + nt * 8 + 2 * t;
                if (c0     > r0g)     sacc[nt][0] = -1e30f;
                if (c0 + 1 > r0g)     sacc[nt][1] = -1e30f;
                if (c0     > r0g + 8) sacc[nt][2] = -1e30f;
                if (c0 + 1 > r0g + 8) sacc[nt][3] = -1e30f;
            }
        }

        float rm[2];
        rm[0] = fmaxf(sacc[0][0], sacc[0][1]);
        rm[1] = fmaxf(sacc[0][2], sacc[0][3]);
#pragma unroll
        for (int nt = 1; nt < 8; nt++) {
            rm[0] = fmaxf(rm[0], fmaxf(sacc[nt][0], sacc[nt][1]));
            rm[1] = fmaxf(rm[1], fmaxf(sacc[nt][2], sacc[nt][3]));
        }
#pragma unroll
        for (int off = 1; off < 4; off <<= 1) {
            rm[0] = fmaxf(rm[0], __shfl_xor_sync(0xffffffffu, rm[0], off));
            rm[1] = fmaxf(rm[1], __shfl_xor_sync(0xffffffffu, rm[1], off));
        }
        float mn0 = fmaxf(m_i[0], rm[0]), mn1 = fmaxf(m_i[1], rm[1]);
        float sc0 = __expf(m_i[0] - mn0), sc1 = __expf(m_i[1] - mn1);
        float rs0 = 0.f, rs1 = 0.f;
#pragma unroll
        for (int nt = 0; nt < 8; nt++) {
            sacc[nt][0] = __expf(sacc[nt][0] - mn0); rs0 += sacc[nt][0];
            sacc[nt][1] = __expf(sacc[nt][1] - mn0); rs0 += sacc[nt][1];
            sacc[nt][2] = __expf(sacc[nt][2] - mn1); rs1 += sacc[nt][2];
            sacc[nt][3] = __expf(sacc[nt][3] - mn1); rs1 += sacc[nt][3];
        }
#pragma unroll
        for (int off = 1; off < 4; off <<= 1) {
            rs0 += __shfl_xor_sync(0xffffffffu, rs0, off);
            rs1 += __shfl_xor_sync(0xffffffffu, rs1, off);
        }
        l_i[0] = l_i[0] * sc0 + rs0;  m_i[0] = mn0;
        l_i[1] = l_i[1] * sc1 + rs1;  m_i[1] = mn1;
#pragma unroll
        for (int nt = 0; nt < 8; nt++) {
            oacc[nt][0] *= sc0; oacc[nt][1] *= sc0;
            oacc[nt][2] *= sc1; oacc[nt][3] *= sc1;
        }

#pragma unroll
        for (int nt = 0; nt < 8; nt++) {
            *(float2*)&Pw[g       * PADP + nt * 8 + 2 * t] = make_float2(sacc[nt][0], sacc[nt][1]);
            *(float2*)&Pw[(g + 8) * PADP + nt * 8 + 2 * t] = make_float2(sacc[nt][2], sacc[nt][3]);
        }
        __syncwarp();

#pragma unroll
        for (int kc8 = 0; kc8 < 8; kc8++) {
            const int kc = kc8 * 8;
            uint32_t araw[4], ah[4], al[4];
            araw[0] = __float_as_uint(Pw[g       * PADP + kc + t]);
            araw[1] = __float_as_uint(Pw[(g + 8) * PADP + kc + t]);
            araw[2] = __float_as_uint(Pw[g       * PADP + kc + t + 4]);
            araw[3] = __float_as_uint(Pw[(g + 8) * PADP + kc + t + 4]);
#pragma unroll
            for (int r = 0; r < 4; r++) tf32_split(araw[r], ah[r], al[r]);
#pragma unroll
            for (int nt = 0; nt < 8; nt++) {
                uint32_t braw[2], bh[2], bl[2];
                braw[0] = __float_as_uint(Vs[(kc + t)     * PADV + nt * 8 + g]);
                braw[1] = __float_as_uint(Vs[(kc + t + 4) * PADV + nt * 8 + g]);
                tf32_split(braw[0], bh[0], bl[0]);
                tf32_split(braw[1], bh[1], bl[1]);
                mma_tf32(oacc[nt], ah, bh);
                mma_tf32(oacc[nt], al, bh);
                mma_tf32(oacc[nt], ah, bl);
            }
        }
        __syncwarp();
    }

    const float inv0 = 1.f / l_i[0], inv1 = 1.f / l_i[1];
    const size_t gr0 = (size_t)(b * SEQ + q0 + wm + g);
    float* ob = out + h * HD;
#pragma unroll
    for (int nt = 0; nt < 8; nt++) {
        int gc = nt * 8 + 2 * t;
        *(float2*)&ob[gr0 * DMODEL + gc] =
            make_float2(oacc[nt][0] * inv0, oacc[nt][1] * inv0);
        *(float2*)&ob[(gr0 + 8) * DMODEL + gc] =
            make_float2(oacc[nt][2] * inv1, oacc[nt][3] * inv1);
    }
}

// ===========================================================================
extern "C" void kernel_launch(void* const* d_in, const int* in_sizes, int n_in,
                              void* d_out, int out_size)
{
    const float* hidden = (const float*)d_in[0];
    const float* w_attn = (const float*)d_in[1];
    const float* b_attn = (const float*)d_in[2];
    const float* w_proj = (const float*)d_in[3];
    const float* b_proj = (const float*)d_in[4];
    float* out = (float*)d_out;

    float* qkv = nullptr;
    float* att = nullptr;
    __nv_bfloat16 *wTh = nullptr, *wTl = nullptr, *xh = nullptr, *xl = nullptr;
    cudaGetSymbolAddress((void**)&qkv, g_qkv);
    cudaGetSymbolAddress((void**)&att, g_att);
    cudaGetSymbolAddress((void**)&wTh, g_wTh);
    cudaGetSymbolAddress((void**)&wTl, g_wTl);
    cudaGetSymbolAddress((void**)&xh,  g_xh);
    cudaGetSymbolAddress((void**)&xl,  g_xl);

    __nv_bfloat16* wTah = wTh;                                 // [3072][1024]
    __nv_bfloat16* wTal = wTl;
    __nv_bfloat16* wTph = wTh + (size_t)QKV_N * DMODEL;        // [1024][1024]
    __nv_bfloat16* wTpl = wTl + (size_t)QKV_N * DMODEL;

    cudaFuncSetAttribute(gemm_bf3, cudaFuncAttributeMaxDynamicSharedMemorySize,
                         GEMM_DYN_SMEM);
    cudaFuncSetAttribute(attn_tc, cudaFuncAttributeMaxDynamicSharedMemorySize,
                         ATTN_SMEM);

    // 0) Weights: transpose + split to packed bf16 hi/lo [N][K]
    {
        dim3 blk(32, 8);
        transpose_split<<<dim3(QKV_N / 32, DMODEL / 32), blk>>>(w_attn, wTah, wTal,
                                                                DMODEL, QKV_N);
        transpose_split<<<dim3(DMODEL / 32, DMODEL / 32), blk>>>(w_proj, wTph, wTpl,
                                                                 DMODEL, DMODEL);
    }

    // 1) hidden -> bf16 hi/lo
    {
        int n4 = (M_ROWS * DMODEL) / 4;
        split_pack<<<(n4 + 255) / 256, 256>>>(hidden, xh, xl, n4);
    }

    // 2) QKV projection (3xbf16 mma): [4096,1024] @ [1024,3072] + bias
    {
        dim3 grid(QKV_N / 256, M_ROWS / 128);
        gemm_bf3<<<grid, 256, GEMM_DYN_SMEM>>>(xh, xl, wTah, wTal, b_attn, qkv,
                                               M_ROWS, QKV_N, DMODEL);
    }

    // 3) Causal attention (3xtf32 mma flash attention)
    {
        dim3 grid(BATCH * NHEAD, SEQ / TQ);
        attn_tc<<<grid, 256, ATTN_SMEM>>>(qkv, att);
    }

    // 4) att -> bf16 hi/lo
    {
        int n4 = (M_ROWS * DMODEL) / 4;
        split_pack<<<(n4 + 255) / 256, 256>>>(att, xh, xl, n4);
    }

    // 5) Output projection (3xbf16 mma): [4096,1024] @ [1024,1024] + bias
    {
        dim3 grid(DMODEL / 256, M_ROWS / 128);
        gemm_bf3<<<grid, 256, GEMM_DYN_SMEM>>>(xh, xl, wTph, wTpl, b_proj, out,
                                               M_ROWS, DMODEL, DMODEL);
    }
}